// round 8
// baseline (speedup 1.0000x reference)
#include <cuda_runtime.h>
#include <cuda_fp16.h>
#include <cstdint>

// Shapes
#define N_Q    65536
#define DIM    64
#define K_EMB  1024
#define QB     128        // queries per block (8 warps x 16 rows)
#define THREADS 256
#define NGROUP 128        // 1024 codes / 8 per n-group
#define PAD    68

#define ESCALE      1024.0f          // exact power-of-2 codebook scaling
#define INV_2SCALE  (1.0f / 512.0f)  // 2*dot = dsum/512 (exact)

#define OUT_QV_ELEMS  (64ULL * 64ULL * 32ULL * 32ULL)   // 4194304
#define OUT_IDX_OFF   4194304ULL
#define OUT_LOSS_OFF  4259840ULL

// device scratch (no cudaMalloc allowed)
__device__ double g_loss;
__device__ float  g_se2[K_EMB];
__device__ float  g_maxNorm[4];   // per-prep-block max scaled row norm
// Packed fp16-hi B fragments for mma.m16n8k16.f16 (codebook scaled by 1024):
// uint4 index (g*2+h)*32+lane holds k-steps {2h, 2h+1} as {b0,b1,b0,b1}.
__device__ uint4  g_b4[NGROUP * 2 * 32];

__device__ __forceinline__ uint32_t pack_h2(__half lo, __half hi) {
    __half2 h = __halves2half2(lo, hi);
    return *reinterpret_cast<uint32_t*>(&h);
}

__device__ __forceinline__ void mma_f16(float& d0, float& d1, float& d2, float& d3,
                                        uint32_t a0, uint32_t a1, uint32_t a2, uint32_t a3,
                                        uint32_t b0, uint32_t b1) {
    asm volatile(
        "mma.sync.aligned.m16n8k16.row.col.f32.f16.f16.f32 "
        "{%0,%1,%2,%3}, {%4,%5,%6,%7}, {%8,%9}, {%0,%1,%2,%3};\n"
        : "+f"(d0), "+f"(d1), "+f"(d2), "+f"(d3)
        : "r"(a0), "r"(a1), "r"(a2), "r"(a3), "r"(b0), "r"(b1));
}

// ---------------------------------------------------------------------------
// Prep: zero loss, ||e||^2, packed fp16-hi B fragments, per-block max norms.
// ---------------------------------------------------------------------------
__global__ void vq_prep(const float* __restrict__ emb) {
    const int t = blockIdx.x * blockDim.x + threadIdx.x;
    if (t == 0) g_loss = 0.0;

    if (t < NGROUP * 2 * 32) {
        const int g = t >> 6;
        const int h = (t >> 5) & 1;
        const int l = t & 31;
        const int gid = l >> 2, tig = l & 3;
        const float* e = emb + (g * 8 + gid) * DIM;
        const int k0 = (2 * h) * 16 + tig * 2;
        const int k1 = (2 * h + 1) * 16 + tig * 2;
        uint4 u;
        u.x = pack_h2(__float2half_rn(e[k0] * ESCALE),     __float2half_rn(e[k0 + 1] * ESCALE));
        u.y = pack_h2(__float2half_rn(e[k0 + 8] * ESCALE), __float2half_rn(e[k0 + 9] * ESCALE));
        u.z = pack_h2(__float2half_rn(e[k1] * ESCALE),     __float2half_rn(e[k1 + 1] * ESCALE));
        u.w = pack_h2(__float2half_rn(e[k1 + 8] * ESCALE), __float2half_rn(e[k1 + 9] * ESCALE));
        g_b4[(g * 2 + h) * 32 + l] = u;
    }

    // se2 + scaled row norms (codes live in blocks 0..3)
    float nrm = 0.0f;
    if (t < K_EMB) {
        const float* e = emb + t * DIM;
        float s = 0.0f;
        #pragma unroll
        for (int j = 0; j < DIM; ++j)
            s = __fadd_rn(s, __fmul_rn(e[j], e[j]));
        g_se2[t] = s;
        nrm = sqrtf(s) * ESCALE;
    }
    if (blockIdx.x < 4) {
        __shared__ float rmx[8];
        float m = nrm;
        #pragma unroll
        for (int off = 16; off > 0; off >>= 1)
            m = fmaxf(m, __shfl_xor_sync(0xFFFFFFFFu, m, off));
        if ((threadIdx.x & 31) == 0) rmx[threadIdx.x >> 5] = m;
        __syncthreads();
        if (threadIdx.x == 0) {
            float mm = rmx[0];
            #pragma unroll
            for (int i = 1; i < 8; ++i) mm = fmaxf(mm, rmx[i]);
            g_maxNorm[blockIdx.x] = mm;
        }
    }
}

// ---------------------------------------------------------------------------
// Main: Phase A = hh-only fp16 MMA screen (pre-packed coalesced fragments)
// with best/second tracking; Phase B = exact fp32 rescan via smem-broadcast
// z reads (NO register hoist -> no spill) for flagged queries.
// ---------------------------------------------------------------------------
__global__ void __launch_bounds__(THREADS, 2)
vq_main(const float* __restrict__ z,
        const float* __restrict__ emb,
        float* __restrict__ out) {
    __shared__ float  sBuf[QB * PAD];   // exact fp32 z tile (kept for phase B)
    __shared__ float  sSe[K_EMB];
    __shared__ float  sSz[QB];
    __shared__ int    sIdx[QB];
    __shared__ int    sFq[QB];
    __shared__ int    sCnt;
    __shared__ float  sMaxE;
    __shared__ double sRed[THREADS / 32];

    const int tid  = threadIdx.x;
    const int wid  = tid >> 5;
    const int lane = tid & 31;
    const int gid  = lane >> 2;
    const int tig  = lane & 3;
    const int qb   = blockIdx.x * QB;

    if (tid == 0) {
        sCnt = 0;
        sMaxE = fmaxf(fmaxf(g_maxNorm[0], g_maxNorm[1]),
                      fmaxf(g_maxNorm[2], g_maxNorm[3]));
    }

    // ---- stage z tile + se ----
    {
        const float4* src = reinterpret_cast<const float4*>(z + (size_t)qb * DIM);
        #pragma unroll
        for (int i = tid; i < QB * (DIM / 4); i += THREADS) {
            int row = i >> 4, c4 = i & 15;
            float4 v = __ldg(src + row * (DIM / 4) + c4);
            *reinterpret_cast<float4*>(&sBuf[row * PAD + 4 * c4]) = v;
        }
        #pragma unroll
        for (int i = tid; i < K_EMB; i += THREADS) sSe[i] = g_se2[i];
    }
    __syncthreads();

    // row norms (square-then-add, sequential; reference style)
    if (tid < QB) {
        const float* r = &sBuf[tid * PAD];
        float s = 0.0f;
        #pragma unroll
        for (int j = 0; j < DIM; ++j)
            s = __fadd_rn(s, __fmul_rn(r[j], r[j]));
        sSz[tid] = s;
    }

    // ---- A fragments (fp16 hi only), rows r0=wid*16+gid, r1=r0+8 ----
    uint32_t aH[4][4];
    const int r0 = wid * 16 + gid;
    const int r1 = r0 + 8;
    #pragma unroll
    for (int s = 0; s < 4; ++s) {
        const int k = s * 16 + tig * 2;
        aH[s][0] = pack_h2(__float2half_rn(sBuf[r0 * PAD + k]),
                           __float2half_rn(sBuf[r0 * PAD + k + 1]));
        aH[s][1] = pack_h2(__float2half_rn(sBuf[r1 * PAD + k]),
                           __float2half_rn(sBuf[r1 * PAD + k + 1]));
        aH[s][2] = pack_h2(__float2half_rn(sBuf[r0 * PAD + k + 8]),
                           __float2half_rn(sBuf[r0 * PAD + k + 9]));
        aH[s][3] = pack_h2(__float2half_rn(sBuf[r1 * PAD + k + 8]),
                           __float2half_rn(sBuf[r1 * PAD + k + 9]));
    }
    __syncthreads();
    const float sz0 = sSz[r0];
    const float sz1 = sSz[r1];

    // ---- Phase A: screen with best + second-best tracking ----
    float b0 = 3.4e38f, s0v = 3.4e38f; int i0 = 0;
    float b1 = 3.4e38f, s1v = 3.4e38f; int i1 = 0;

    #pragma unroll 2
    for (int g = 0; g < NGROUP; ++g) {
        const uint4 U0 = __ldg(&g_b4[(g * 2) * 32 + lane]);
        const uint4 U1 = __ldg(&g_b4[(g * 2 + 1) * 32 + lane]);
        float d0 = 0.f, d1 = 0.f, d2 = 0.f, d3 = 0.f;
        mma_f16(d0, d1, d2, d3, aH[0][0], aH[0][1], aH[0][2], aH[0][3], U0.x, U0.y);
        mma_f16(d0, d1, d2, d3, aH[1][0], aH[1][1], aH[1][2], aH[1][3], U0.z, U0.w);
        mma_f16(d0, d1, d2, d3, aH[2][0], aH[2][1], aH[2][2], aH[2][3], U1.x, U1.y);
        mma_f16(d0, d1, d2, d3, aH[3][0], aH[3][1], aH[3][2], aH[3][3], U1.z, U1.w);

        const int c0 = g * 8 + 2 * tig;
        const float se0 = sSe[c0], se1 = sSe[c0 + 1];
        const float q00 = sz0 - d0 * INV_2SCALE + se0;
        const float q01 = sz0 - d1 * INV_2SCALE + se1;
        const float q10 = sz1 - d2 * INV_2SCALE + se0;
        const float q11 = sz1 - d3 * INV_2SCALE + se1;

        if (q00 < b0) { s0v = b0; b0 = q00; i0 = c0; }     else if (q00 < s0v) s0v = q00;
        if (q01 < b0) { s0v = b0; b0 = q01; i0 = c0 + 1; } else if (q01 < s0v) s0v = q01;
        if (q10 < b1) { s1v = b1; b1 = q10; i1 = c0; }     else if (q10 < s1v) s1v = q10;
        if (q11 < b1) { s1v = b1; b1 = q11; i1 = c0 + 1; } else if (q11 < s1v) s1v = q11;
    }

    // ---- quad butterfly reduce (best, idx, second) per row ----
    #pragma unroll
    for (int off = 1; off <= 2; off <<= 1) {
        float ob = __shfl_xor_sync(0xFFFFFFFFu, b0, off);
        int   oi = __shfl_xor_sync(0xFFFFFFFFu, i0, off);
        float os = __shfl_xor_sync(0xFFFFFFFFu, s0v, off);
        if (ob < b0) { s0v = fminf(b0, os); b0 = ob; i0 = oi; }
        else         { s0v = fminf(s0v, ob); }
        float ob1 = __shfl_xor_sync(0xFFFFFFFFu, b1, off);
        int   oi1 = __shfl_xor_sync(0xFFFFFFFFu, i1, off);
        float os1 = __shfl_xor_sync(0xFFFFFFFFu, s1v, off);
        if (ob1 < b1) { s1v = fminf(b1, os1); b1 = ob1; i1 = oi1; }
        else          { s1v = fminf(s1v, ob1); }
    }

    if (tig == 0) {
        const float mE = sMaxE;
        sIdx[r0] = i0;
        sIdx[r1] = i1;
        // rigorous rescue margin: 2x provable hh-screen error + slack
        const float m0 = sqrtf(sz0) * mE * 4.0e-6f + 1.2e-4f;
        const float m1 = sqrtf(sz1) * mE * 4.0e-6f + 1.2e-4f;
        if (s0v - b0 <= m0) { int p = atomicAdd(&sCnt, 1); sFq[p] = r0; }
        if (s1v - b1 <= m1) { int p = atomicAdd(&sCnt, 1); sFq[p] = r1; }
    }
    __syncthreads();

    // ---- Phase B: exact fp32 rescan, z via smem broadcast (no reg hoist) ----
    const int cnt = sCnt;
    for (int f = wid; f < cnt; f += THREADS / 32) {
        const int q = sFq[f];
        const float szq = sSz[q];
        const float4* zq4 = reinterpret_cast<const float4*>(&sBuf[q * PAD]);
        float best = 3.4e38f; int bi = 0;
        for (int c = lane; c < K_EMB; c += 32) {
            const float4* e4 = reinterpret_cast<const float4*>(emb + (size_t)c * DIM);
            float a0 = 0.f, a1 = 0.f, a2 = 0.f, a3 = 0.f;
            #pragma unroll
            for (int j = 0; j < DIM / 4; ++j) {
                float4 e = __ldg(e4 + j);
                float4 zv = zq4[j];            // broadcast LDS.128
                a0 = fmaf(zv.x, e.x, a0);
                a1 = fmaf(zv.y, e.y, a1);
                a2 = fmaf(zv.z, e.z, a2);
                a3 = fmaf(zv.w, e.w, a3);
            }
            float dot = __fadd_rn(__fadd_rn(a0, a1), __fadd_rn(a2, a3));
            float d2 = __fadd_rn(__fsub_rn(szq, __fmul_rn(2.0f, dot)), sSe[c]);
            if (d2 < best) { best = d2; bi = c; }   // ascending c: first-index
        }
        #pragma unroll
        for (int off = 16; off > 0; off >>= 1) {
            float ov = __shfl_down_sync(0xFFFFFFFFu, best, off);
            int   oi = __shfl_down_sync(0xFFFFFFFFu, bi, off);
            if (ov < best || (ov == best && oi < bi)) { best = ov; bi = oi; }
        }
        if (lane == 0) sIdx[q] = bi;
    }
    __syncthreads();

    // ---- outputs: gather, STE, idx, loss ----
    double lsum = 0.0;
    if (tid < QB) {
        const int n = qb + tid;
        const int bidx = sIdx[tid];
        const int w = n & 31;
        const int h = (n >> 5) & 31;
        const int b = n >> 10;
        const size_t obase = (size_t)b * 65536 + (size_t)h * 32 + w;

        const float4* zrow = reinterpret_cast<const float4*>(z + (size_t)n * DIM);
        const float*  eb   = emb + (size_t)bidx * DIM;
        #pragma unroll
        for (int i4 = 0; i4 < DIM / 4; ++i4) {
            float4 zq4 = __ldg(zrow + i4);
            float zq[4] = {zq4.x, zq4.y, zq4.z, zq4.w};
            #pragma unroll
            for (int j = 0; j < 4; ++j) {
                const int d = 4 * i4 + j;
                float q = __ldg(eb + d);
                float diff = __fsub_rn(q, zq[j]);
                out[obase + (size_t)d * 1024] = __fadd_rn(zq[j], diff);  // STE
                lsum += (double)diff * (double)diff;
            }
        }
        out[OUT_IDX_OFF + (size_t)n] = (float)bidx;
    }

    // ---- loss reduction ----
    #pragma unroll
    for (int off = 16; off > 0; off >>= 1)
        lsum += __shfl_down_sync(0xFFFFFFFFu, lsum, off);
    if (lane == 0) sRed[wid] = lsum;
    __syncthreads();
    if (tid == 0) {
        double v = 0.0;
        #pragma unroll
        for (int i = 0; i < THREADS / 32; ++i) v += sRed[i];
        atomicAdd(&g_loss, v);
    }
}

// ---------------------------------------------------------------------------
__global__ void vq_fin(float* __restrict__ out) {
    if (threadIdx.x == 0 && blockIdx.x == 0) {
        double mean = g_loss / (double)OUT_QV_ELEMS;
        out[OUT_LOSS_OFF] = (float)(mean * 0.25 + mean * 1.0);
    }
}

extern "C" void kernel_launch(void* const* d_in, const int* in_sizes, int n_in,
                              void* d_out, int out_size) {
    const float* z   = (const float*)d_in[0];
    const float* emb = (const float*)d_in[1];
    float* out = (float*)d_out;

    vq_prep<<<(NGROUP * 2 * 32 + 255) / 256, 256>>>(emb);
    vq_main<<<N_Q / QB, THREADS>>>(z, emb, out);
    vq_fin<<<1, 32>>>(out);
}

// round 9
// speedup vs baseline: 1.6009x; 1.6009x over previous
#include <cuda_runtime.h>
#include <cuda_fp16.h>
#include <cstdint>

// Shapes
#define N_Q    65536
#define DIM    64
#define K_EMB  1024
#define QB     128        // queries per block (8 warps x 16 rows)
#define THREADS 256
#define NBLOCKS (N_Q / QB)   // 512
#define NGROUP 128        // 1024 codes / 8 per n-group
#define PAD    68

#define ESCALE      1024.0f          // exact power-of-2 codebook scaling
#define INV_2SCALE  (1.0f / 512.0f)  // 2*dot = dsum/512 (exact)
#define FLAG_BIT    0x40000000u

#define OUT_QV_ELEMS  (64ULL * 64ULL * 32ULL * 32ULL)   // 4194304
#define OUT_IDX_OFF   4194304ULL
#define OUT_LOSS_OFF  4259840ULL

// device scratch (no cudaMalloc; zero-initialized at load)
__device__ float    g_se2[K_EMB];
__device__ float    g_maxNorm[4];
__device__ uint4    g_b4[NGROUP * 2 * 32];   // packed fp16-hi B fragments
__device__ unsigned g_idx[N_Q];              // approx idx | FLAG_BIT
__device__ double   g_partial[NBLOCKS];
__device__ unsigned g_done;                  // monotonic; 2^32 % 512 == 0

__device__ __forceinline__ uint32_t pack_h2(__half lo, __half hi) {
    __half2 h = __halves2half2(lo, hi);
    return *reinterpret_cast<uint32_t*>(&h);
}

__device__ __forceinline__ void mma_f16(float& d0, float& d1, float& d2, float& d3,
                                        uint32_t a0, uint32_t a1, uint32_t a2, uint32_t a3,
                                        uint32_t b0, uint32_t b1) {
    asm volatile(
        "mma.sync.aligned.m16n8k16.row.col.f32.f16.f16.f32 "
        "{%0,%1,%2,%3}, {%4,%5,%6,%7}, {%8,%9}, {%0,%1,%2,%3};\n"
        : "+f"(d0), "+f"(d1), "+f"(d2), "+f"(d3)
        : "r"(a0), "r"(a1), "r"(a2), "r"(a3), "r"(b0), "r"(b1));
}

// ---------------------------------------------------------------------------
// Prep: ||e||^2, packed fp16-hi fragments, per-block max scaled norms.
// ---------------------------------------------------------------------------
__global__ void vq_prep(const float* __restrict__ emb) {
    const int t = blockIdx.x * blockDim.x + threadIdx.x;

    if (t < NGROUP * 2 * 32) {
        const int g = t >> 6;
        const int h = (t >> 5) & 1;
        const int l = t & 31;
        const int gid = l >> 2, tig = l & 3;
        const float* e = emb + (g * 8 + gid) * DIM;
        const int k0 = (2 * h) * 16 + tig * 2;
        const int k1 = (2 * h + 1) * 16 + tig * 2;
        uint4 u;
        u.x = pack_h2(__float2half_rn(e[k0] * ESCALE),     __float2half_rn(e[k0 + 1] * ESCALE));
        u.y = pack_h2(__float2half_rn(e[k0 + 8] * ESCALE), __float2half_rn(e[k0 + 9] * ESCALE));
        u.z = pack_h2(__float2half_rn(e[k1] * ESCALE),     __float2half_rn(e[k1 + 1] * ESCALE));
        u.w = pack_h2(__float2half_rn(e[k1 + 8] * ESCALE), __float2half_rn(e[k1 + 9] * ESCALE));
        g_b4[(g * 2 + h) * 32 + l] = u;
    }

    float nrm = 0.0f;
    if (t < K_EMB) {
        const float* e = emb + t * DIM;
        float s = 0.0f;
        #pragma unroll
        for (int j = 0; j < DIM; ++j)
            s = __fadd_rn(s, __fmul_rn(e[j], e[j]));
        g_se2[t] = s;
        nrm = sqrtf(s) * ESCALE;
    }
    if (blockIdx.x < 4) {
        __shared__ float rmx[8];
        float m = nrm;
        #pragma unroll
        for (int off = 16; off > 0; off >>= 1)
            m = fmaxf(m, __shfl_xor_sync(0xFFFFFFFFu, m, off));
        if ((threadIdx.x & 31) == 0) rmx[threadIdx.x >> 5] = m;
        __syncthreads();
        if (threadIdx.x == 0) {
            float mm = rmx[0];
            #pragma unroll
            for (int i = 1; i < 8; ++i) mm = fmaxf(mm, rmx[i]);
            g_maxNorm[blockIdx.x] = mm;
        }
    }
}

// ---------------------------------------------------------------------------
// Screen: hh-only fp16 MMA argmin with best/second tracking. NO rescan code
// in this kernel -> low register pressure, no spills. Writes idx|flag.
// ---------------------------------------------------------------------------
__global__ void __launch_bounds__(THREADS, 2)
vq_screen(const float* __restrict__ z) {
    __shared__ float sBuf[QB * PAD];
    __shared__ float sSe[K_EMB];
    __shared__ float sSz[QB];
    __shared__ float sMaxE;

    const int tid  = threadIdx.x;
    const int wid  = tid >> 5;
    const int lane = tid & 31;
    const int gid  = lane >> 2;
    const int tig  = lane & 3;
    const int qb   = blockIdx.x * QB;

    if (tid == 0)
        sMaxE = fmaxf(fmaxf(g_maxNorm[0], g_maxNorm[1]),
                      fmaxf(g_maxNorm[2], g_maxNorm[3]));

    // stage z tile + se
    {
        const float4* src = reinterpret_cast<const float4*>(z + (size_t)qb * DIM);
        #pragma unroll
        for (int i = tid; i < QB * (DIM / 4); i += THREADS) {
            int row = i >> 4, c4 = i & 15;
            float4 v = __ldg(src + row * (DIM / 4) + c4);
            *reinterpret_cast<float4*>(&sBuf[row * PAD + 4 * c4]) = v;
        }
        #pragma unroll
        for (int i = tid; i < K_EMB; i += THREADS) sSe[i] = g_se2[i];
    }
    __syncthreads();

    if (tid < QB) {
        const float* r = &sBuf[tid * PAD];
        float s = 0.0f;
        #pragma unroll
        for (int j = 0; j < DIM; ++j)
            s = __fadd_rn(s, __fmul_rn(r[j], r[j]));
        sSz[tid] = s;
    }

    // A fragments (fp16 hi only)
    uint32_t aH[4][4];
    const int r0 = wid * 16 + gid;
    const int r1 = r0 + 8;
    #pragma unroll
    for (int s = 0; s < 4; ++s) {
        const int k = s * 16 + tig * 2;
        aH[s][0] = pack_h2(__float2half_rn(sBuf[r0 * PAD + k]),
                           __float2half_rn(sBuf[r0 * PAD + k + 1]));
        aH[s][1] = pack_h2(__float2half_rn(sBuf[r1 * PAD + k]),
                           __float2half_rn(sBuf[r1 * PAD + k + 1]));
        aH[s][2] = pack_h2(__float2half_rn(sBuf[r0 * PAD + k + 8]),
                           __float2half_rn(sBuf[r0 * PAD + k + 9]));
        aH[s][3] = pack_h2(__float2half_rn(sBuf[r1 * PAD + k + 8]),
                           __float2half_rn(sBuf[r1 * PAD + k + 9]));
    }
    __syncthreads();
    const float sz0 = sSz[r0];
    const float sz1 = sSz[r1];

    float b0 = 3.4e38f, s0v = 3.4e38f; int i0 = 0;
    float b1 = 3.4e38f, s1v = 3.4e38f; int i1 = 0;

    #pragma unroll 2
    for (int g = 0; g < NGROUP; ++g) {
        const uint4 U0 = __ldg(&g_b4[(g * 2) * 32 + lane]);
        const uint4 U1 = __ldg(&g_b4[(g * 2 + 1) * 32 + lane]);
        float d0 = 0.f, d1 = 0.f, d2 = 0.f, d3 = 0.f;
        mma_f16(d0, d1, d2, d3, aH[0][0], aH[0][1], aH[0][2], aH[0][3], U0.x, U0.y);
        mma_f16(d0, d1, d2, d3, aH[1][0], aH[1][1], aH[1][2], aH[1][3], U0.z, U0.w);
        mma_f16(d0, d1, d2, d3, aH[2][0], aH[2][1], aH[2][2], aH[2][3], U1.x, U1.y);
        mma_f16(d0, d1, d2, d3, aH[3][0], aH[3][1], aH[3][2], aH[3][3], U1.z, U1.w);

        const int c0 = g * 8 + 2 * tig;
        const float se0 = sSe[c0], se1 = sSe[c0 + 1];
        const float q00 = sz0 - d0 * INV_2SCALE + se0;
        const float q01 = sz0 - d1 * INV_2SCALE + se1;
        const float q10 = sz1 - d2 * INV_2SCALE + se0;
        const float q11 = sz1 - d3 * INV_2SCALE + se1;

        if (q00 < b0) { s0v = b0; b0 = q00; i0 = c0; }     else if (q00 < s0v) s0v = q00;
        if (q01 < b0) { s0v = b0; b0 = q01; i0 = c0 + 1; } else if (q01 < s0v) s0v = q01;
        if (q10 < b1) { s1v = b1; b1 = q10; i1 = c0; }     else if (q10 < s1v) s1v = q10;
        if (q11 < b1) { s1v = b1; b1 = q11; i1 = c0 + 1; } else if (q11 < s1v) s1v = q11;
    }

    // quad butterfly reduce (best, idx, second)
    #pragma unroll
    for (int off = 1; off <= 2; off <<= 1) {
        float ob = __shfl_xor_sync(0xFFFFFFFFu, b0, off);
        int   oi = __shfl_xor_sync(0xFFFFFFFFu, i0, off);
        float os = __shfl_xor_sync(0xFFFFFFFFu, s0v, off);
        if (ob < b0) { s0v = fminf(b0, os); b0 = ob; i0 = oi; }
        else         { s0v = fminf(s0v, ob); }
        float ob1 = __shfl_xor_sync(0xFFFFFFFFu, b1, off);
        int   oi1 = __shfl_xor_sync(0xFFFFFFFFu, i1, off);
        float os1 = __shfl_xor_sync(0xFFFFFFFFu, s1v, off);
        if (ob1 < b1) { s1v = fminf(b1, os1); b1 = ob1; i1 = oi1; }
        else          { s1v = fminf(s1v, ob1); }
    }

    if (tig == 0) {
        const float mE = sMaxE;
        const float m0 = sqrtf(sz0) * mE * 4.0e-6f + 1.2e-4f;
        const float m1 = sqrtf(sz1) * mE * 4.0e-6f + 1.2e-4f;
        unsigned v0 = (unsigned)i0 | ((s0v - b0 <= m0) ? FLAG_BIT : 0u);
        unsigned v1 = (unsigned)i1 | ((s1v - b1 <= m1) ? FLAG_BIT : 0u);
        g_idx[qb + r0] = v0;
        g_idx[qb + r1] = v1;
    }
}

// ---------------------------------------------------------------------------
// Finish: rescue flagged queries (exact fp32, reference rounding), then
// gather/STE/idx/loss; loss finalized by last block.
// ---------------------------------------------------------------------------
__global__ void __launch_bounds__(THREADS, 2)
vq_finish(const float* __restrict__ z,
          const float* __restrict__ emb,
          float* __restrict__ out) {
    __shared__ float  sBuf[QB * PAD];
    __shared__ float  sSe[K_EMB];
    __shared__ float  sSz[QB];
    __shared__ int    sIdx[QB];
    __shared__ int    sFq[QB];
    __shared__ int    sCnt;
    __shared__ int    sLast;
    __shared__ double sRed[THREADS / 32];

    const int tid  = threadIdx.x;
    const int wid  = tid >> 5;
    const int lane = tid & 31;
    const int qb   = blockIdx.x * QB;

    if (tid == 0) { sCnt = 0; sLast = 0; }

    // stage z tile + se
    {
        const float4* src = reinterpret_cast<const float4*>(z + (size_t)qb * DIM);
        #pragma unroll
        for (int i = tid; i < QB * (DIM / 4); i += THREADS) {
            int row = i >> 4, c4 = i & 15;
            float4 v = __ldg(src + row * (DIM / 4) + c4);
            *reinterpret_cast<float4*>(&sBuf[row * PAD + 4 * c4]) = v;
        }
        #pragma unroll
        for (int i = tid; i < K_EMB; i += THREADS) sSe[i] = g_se2[i];
    }
    __syncthreads();

    // row norms + load idx/flags
    if (tid < QB) {
        const float* r = &sBuf[tid * PAD];
        float s = 0.0f;
        #pragma unroll
        for (int j = 0; j < DIM; ++j)
            s = __fadd_rn(s, __fmul_rn(r[j], r[j]));
        sSz[tid] = s;

        unsigned v = g_idx[qb + tid];
        sIdx[tid] = (int)(v & 0x3FFu);
        if (v & FLAG_BIT) { int p = atomicAdd(&sCnt, 1); sFq[p] = tid; }
    }
    __syncthreads();

    // rescue: exact fp32 full rescan, z via smem broadcast
    const int cnt = sCnt;
    for (int f = wid; f < cnt; f += THREADS / 32) {
        const int q = sFq[f];
        const float szq = sSz[q];
        const float4* zq4 = reinterpret_cast<const float4*>(&sBuf[q * PAD]);
        float best = 3.4e38f; int bi = 0;
        for (int c = lane; c < K_EMB; c += 32) {
            const float4* e4 = reinterpret_cast<const float4*>(emb + (size_t)c * DIM);
            float a0 = 0.f, a1 = 0.f, a2 = 0.f, a3 = 0.f;
            #pragma unroll
            for (int j = 0; j < DIM / 4; ++j) {
                float4 e = __ldg(e4 + j);
                float4 zv = zq4[j];            // broadcast LDS.128
                a0 = fmaf(zv.x, e.x, a0);
                a1 = fmaf(zv.y, e.y, a1);
                a2 = fmaf(zv.z, e.z, a2);
                a3 = fmaf(zv.w, e.w, a3);
            }
            float dot = __fadd_rn(__fadd_rn(a0, a1), __fadd_rn(a2, a3));
            float d2 = __fadd_rn(__fsub_rn(szq, __fmul_rn(2.0f, dot)), sSe[c]);
            if (d2 < best) { best = d2; bi = c; }   // ascending c: first-index
        }
        #pragma unroll
        for (int off = 16; off > 0; off >>= 1) {
            float ov = __shfl_down_sync(0xFFFFFFFFu, best, off);
            int   oi = __shfl_down_sync(0xFFFFFFFFu, bi, off);
            if (ov < best || (ov == best && oi < bi)) { best = ov; bi = oi; }
        }
        if (lane == 0) sIdx[q] = bi;
    }
    __syncthreads();

    // outputs: gather, STE, idx, loss partial
    double lsum = 0.0;
    if (tid < QB) {
        const int n = qb + tid;
        const int bidx = sIdx[tid];
        const int w = n & 31;
        const int h = (n >> 5) & 31;
        const int b = n >> 10;
        const size_t obase = (size_t)b * 65536 + (size_t)h * 32 + w;

        const float* zr = &sBuf[tid * PAD];
        const float* eb = emb + (size_t)bidx * DIM;
        #pragma unroll
        for (int d = 0; d < DIM; ++d) {
            float zq = zr[d];
            float q  = __ldg(eb + d);
            float diff = __fsub_rn(q, zq);
            out[obase + (size_t)d * 1024] = __fadd_rn(zq, diff);  // STE
            lsum += (double)diff * (double)diff;
        }
        out[OUT_IDX_OFF + (size_t)n] = (float)bidx;
    }

    // block loss reduction + last-block finalize
    #pragma unroll
    for (int off = 16; off > 0; off >>= 1)
        lsum += __shfl_down_sync(0xFFFFFFFFu, lsum, off);
    if (lane == 0) sRed[wid] = lsum;
    __syncthreads();
    if (tid == 0) {
        double v = 0.0;
        #pragma unroll
        for (int i = 0; i < THREADS / 32; ++i) v += sRed[i];
        g_partial[blockIdx.x] = v;
        __threadfence();
        unsigned old = atomicAdd(&g_done, 1u);
        if ((old & (NBLOCKS - 1)) == (NBLOCKS - 1)) sLast = 1;
    }
    __syncthreads();

    if (sLast && wid == 0) {
        __threadfence();
        double v = 0.0;
        #pragma unroll
        for (int i = 0; i < NBLOCKS / 32; ++i)      // fixed order: deterministic
            v += g_partial[lane + i * 32];
        #pragma unroll
        for (int off = 16; off > 0; off >>= 1)
            v += __shfl_down_sync(0xFFFFFFFFu, v, off);
        if (lane == 0) {
            double mean = v / (double)OUT_QV_ELEMS;
            out[OUT_LOSS_OFF] = (float)(mean * 0.25 + mean * 1.0);
        }
    }
}

extern "C" void kernel_launch(void* const* d_in, const int* in_sizes, int n_in,
                              void* d_out, int out_size) {
    const float* z   = (const float*)d_in[0];
    const float* emb = (const float*)d_in[1];
    float* out = (float*)d_out;

    vq_prep<<<(NGROUP * 2 * 32 + 255) / 256, 256>>>(emb);
    vq_screen<<<NBLOCKS, THREADS>>>(z);
    vq_finish<<<NBLOCKS, THREADS>>>(z, emb, out);
}

// round 10
// speedup vs baseline: 6.3545x; 3.9693x over previous
#include <cuda_runtime.h>
#include <cuda_fp16.h>
#include <cstdint>

// Shapes
#define N_Q    65536
#define DIM    64
#define K_EMB  1024
#define QB     128        // queries per block (8 warps x 16 rows)
#define THREADS 256
#define NBLOCKS (N_Q / QB)   // 512
#define NGROUP 128        // 1024 codes / 8 per n-group
#define PAD    68         // row stride (floats): 272 B, 16B-aligned

#define ESCALE      1024.0f
#define INV_2SCALE  (1.0f / 512.0f)
#define FLAG_BIT    0x40000000u

#define OUT_QV_ELEMS  (64ULL * 64ULL * 32ULL * 32ULL)   // 4194304
#define OUT_IDX_OFF   4194304ULL
#define OUT_LOSS_OFF  4259840ULL

// ---- finish-kernel dynamic smem layout (byte offsets) ----
#define SRED_OFF    0        // double[8]
#define SCNT_OFF    64
#define SLAST_OFF   68
#define SIDX_OFF    80       // int[128]
#define SFQ_OFF     592      // int[128]
#define SFBI_OFF    1104     // int[128]
#define SFBEST_OFF  1616     // float[128]
#define SSZ_OFF     2176     // float[128]
#define SSE_OFF     2688     // float[1024]
#define SBUF_OFF    6784     // float[128*68]  (z tile)
#define SE_OFF      41600    // float[128*68]  (codebook chunk)
#define SMEM_FIN    76416

// device scratch (no cudaMalloc; zero-initialized at load)
__device__ float    g_se2[K_EMB];
__device__ float    g_maxNorm[4];
__device__ uint4    g_b4[NGROUP * 2 * 32];
__device__ unsigned g_idx[N_Q];
__device__ double   g_partial[NBLOCKS];
__device__ unsigned g_done;                  // monotonic; 2^32 % 512 == 0

__device__ __forceinline__ uint32_t pack_h2(__half lo, __half hi) {
    __half2 h = __halves2half2(lo, hi);
    return *reinterpret_cast<uint32_t*>(&h);
}

__device__ __forceinline__ void mma_f16(float& d0, float& d1, float& d2, float& d3,
                                        uint32_t a0, uint32_t a1, uint32_t a2, uint32_t a3,
                                        uint32_t b0, uint32_t b1) {
    asm volatile(
        "mma.sync.aligned.m16n8k16.row.col.f32.f16.f16.f32 "
        "{%0,%1,%2,%3}, {%4,%5,%6,%7}, {%8,%9}, {%0,%1,%2,%3};\n"
        : "+f"(d0), "+f"(d1), "+f"(d2), "+f"(d3)
        : "r"(a0), "r"(a1), "r"(a2), "r"(a3), "r"(b0), "r"(b1));
}

// ---------------------------------------------------------------------------
// Prep (unchanged): ||e||^2, packed fp16-hi fragments, per-block max norms.
// ---------------------------------------------------------------------------
__global__ void vq_prep(const float* __restrict__ emb) {
    const int t = blockIdx.x * blockDim.x + threadIdx.x;

    if (t < NGROUP * 2 * 32) {
        const int g = t >> 6;
        const int h = (t >> 5) & 1;
        const int l = t & 31;
        const int gid = l >> 2, tig = l & 3;
        const float* e = emb + (g * 8 + gid) * DIM;
        const int k0 = (2 * h) * 16 + tig * 2;
        const int k1 = (2 * h + 1) * 16 + tig * 2;
        uint4 u;
        u.x = pack_h2(__float2half_rn(e[k0] * ESCALE),     __float2half_rn(e[k0 + 1] * ESCALE));
        u.y = pack_h2(__float2half_rn(e[k0 + 8] * ESCALE), __float2half_rn(e[k0 + 9] * ESCALE));
        u.z = pack_h2(__float2half_rn(e[k1] * ESCALE),     __float2half_rn(e[k1 + 1] * ESCALE));
        u.w = pack_h2(__float2half_rn(e[k1 + 8] * ESCALE), __float2half_rn(e[k1 + 9] * ESCALE));
        g_b4[(g * 2 + h) * 32 + l] = u;
    }

    float nrm = 0.0f;
    if (t < K_EMB) {
        const float* e = emb + t * DIM;
        float s = 0.0f;
        #pragma unroll
        for (int j = 0; j < DIM; ++j)
            s = __fadd_rn(s, __fmul_rn(e[j], e[j]));
        g_se2[t] = s;
        nrm = sqrtf(s) * ESCALE;
    }
    if (blockIdx.x < 4) {
        __shared__ float rmx[8];
        float m = nrm;
        #pragma unroll
        for (int off = 16; off > 0; off >>= 1)
            m = fmaxf(m, __shfl_xor_sync(0xFFFFFFFFu, m, off));
        if ((threadIdx.x & 31) == 0) rmx[threadIdx.x >> 5] = m;
        __syncthreads();
        if (threadIdx.x == 0) {
            float mm = rmx[0];
            #pragma unroll
            for (int i = 1; i < 8; ++i) mm = fmaxf(mm, rmx[i]);
            g_maxNorm[blockIdx.x] = mm;
        }
    }
}

// ---------------------------------------------------------------------------
// Screen (unchanged from R9): hh-only fp16 MMA, best/second, writes idx|flag.
// ---------------------------------------------------------------------------
__global__ void __launch_bounds__(THREADS, 2)
vq_screen(const float* __restrict__ z) {
    __shared__ float sBuf[QB * PAD];
    __shared__ float sSe[K_EMB];
    __shared__ float sSz[QB];
    __shared__ float sMaxE;

    const int tid  = threadIdx.x;
    const int wid  = tid >> 5;
    const int lane = tid & 31;
    const int gid  = lane >> 2;
    const int tig  = lane & 3;
    const int qb   = blockIdx.x * QB;

    if (tid == 0)
        sMaxE = fmaxf(fmaxf(g_maxNorm[0], g_maxNorm[1]),
                      fmaxf(g_maxNorm[2], g_maxNorm[3]));

    {
        const float4* src = reinterpret_cast<const float4*>(z + (size_t)qb * DIM);
        #pragma unroll
        for (int i = tid; i < QB * (DIM / 4); i += THREADS) {
            int row = i >> 4, c4 = i & 15;
            float4 v = __ldg(src + row * (DIM / 4) + c4);
            *reinterpret_cast<float4*>(&sBuf[row * PAD + 4 * c4]) = v;
        }
        #pragma unroll
        for (int i = tid; i < K_EMB; i += THREADS) sSe[i] = g_se2[i];
    }
    __syncthreads();

    if (tid < QB) {
        const float* r = &sBuf[tid * PAD];
        float s = 0.0f;
        #pragma unroll
        for (int j = 0; j < DIM; ++j)
            s = __fadd_rn(s, __fmul_rn(r[j], r[j]));
        sSz[tid] = s;
    }

    uint32_t aH[4][4];
    const int r0 = wid * 16 + gid;
    const int r1 = r0 + 8;
    #pragma unroll
    for (int s = 0; s < 4; ++s) {
        const int k = s * 16 + tig * 2;
        aH[s][0] = pack_h2(__float2half_rn(sBuf[r0 * PAD + k]),
                           __float2half_rn(sBuf[r0 * PAD + k + 1]));
        aH[s][1] = pack_h2(__float2half_rn(sBuf[r1 * PAD + k]),
                           __float2half_rn(sBuf[r1 * PAD + k + 1]));
        aH[s][2] = pack_h2(__float2half_rn(sBuf[r0 * PAD + k + 8]),
                           __float2half_rn(sBuf[r0 * PAD + k + 9]));
        aH[s][3] = pack_h2(__float2half_rn(sBuf[r1 * PAD + k + 8]),
                           __float2half_rn(sBuf[r1 * PAD + k + 9]));
    }
    __syncthreads();
    const float sz0 = sSz[r0];
    const float sz1 = sSz[r1];

    float b0 = 3.4e38f, s0v = 3.4e38f; int i0 = 0;
    float b1 = 3.4e38f, s1v = 3.4e38f; int i1 = 0;

    #pragma unroll 2
    for (int g = 0; g < NGROUP; ++g) {
        const uint4 U0 = __ldg(&g_b4[(g * 2) * 32 + lane]);
        const uint4 U1 = __ldg(&g_b4[(g * 2 + 1) * 32 + lane]);
        float d0 = 0.f, d1 = 0.f, d2 = 0.f, d3 = 0.f;
        mma_f16(d0, d1, d2, d3, aH[0][0], aH[0][1], aH[0][2], aH[0][3], U0.x, U0.y);
        mma_f16(d0, d1, d2, d3, aH[1][0], aH[1][1], aH[1][2], aH[1][3], U0.z, U0.w);
        mma_f16(d0, d1, d2, d3, aH[2][0], aH[2][1], aH[2][2], aH[2][3], U1.x, U1.y);
        mma_f16(d0, d1, d2, d3, aH[3][0], aH[3][1], aH[3][2], aH[3][3], U1.z, U1.w);

        const int c0 = g * 8 + 2 * tig;
        const float se0 = sSe[c0], se1 = sSe[c0 + 1];
        const float q00 = sz0 - d0 * INV_2SCALE + se0;
        const float q01 = sz0 - d1 * INV_2SCALE + se1;
        const float q10 = sz1 - d2 * INV_2SCALE + se0;
        const float q11 = sz1 - d3 * INV_2SCALE + se1;

        if (q00 < b0) { s0v = b0; b0 = q00; i0 = c0; }     else if (q00 < s0v) s0v = q00;
        if (q01 < b0) { s0v = b0; b0 = q01; i0 = c0 + 1; } else if (q01 < s0v) s0v = q01;
        if (q10 < b1) { s1v = b1; b1 = q10; i1 = c0; }     else if (q10 < s1v) s1v = q10;
        if (q11 < b1) { s1v = b1; b1 = q11; i1 = c0 + 1; } else if (q11 < s1v) s1v = q11;
    }

    #pragma unroll
    for (int off = 1; off <= 2; off <<= 1) {
        float ob = __shfl_xor_sync(0xFFFFFFFFu, b0, off);
        int   oi = __shfl_xor_sync(0xFFFFFFFFu, i0, off);
        float os = __shfl_xor_sync(0xFFFFFFFFu, s0v, off);
        if (ob < b0) { s0v = fminf(b0, os); b0 = ob; i0 = oi; }
        else         { s0v = fminf(s0v, ob); }
        float ob1 = __shfl_xor_sync(0xFFFFFFFFu, b1, off);
        int   oi1 = __shfl_xor_sync(0xFFFFFFFFu, i1, off);
        float os1 = __shfl_xor_sync(0xFFFFFFFFu, s1v, off);
        if (ob1 < b1) { s1v = fminf(b1, os1); b1 = ob1; i1 = oi1; }
        else          { s1v = fminf(s1v, ob1); }
    }

    if (tig == 0) {
        const float mE = sMaxE;
        const float m0 = sqrtf(sz0) * mE * 4.0e-6f + 1.2e-4f;
        const float m1 = sqrtf(sz1) * mE * 4.0e-6f + 1.2e-4f;
        g_idx[qb + r0] = (unsigned)i0 | ((s0v - b0 <= m0) ? FLAG_BIT : 0u);
        g_idx[qb + r1] = (unsigned)i1 | ((s1v - b1 <= m1) ? FLAG_BIT : 0u);
    }
}

// ---------------------------------------------------------------------------
// Finish: rescue flagged queries via SMEM-STAGED codebook chunks (coalesced
// staging, padded LDS reads — no 32-sector LDG storms), then outputs + loss.
// ---------------------------------------------------------------------------
__global__ void __launch_bounds__(THREADS, 2)
vq_finish(const float* __restrict__ z,
          const float* __restrict__ emb,
          float* __restrict__ out) {
    extern __shared__ __align__(16) char sm[];
    double* sRed   = reinterpret_cast<double*>(sm + SRED_OFF);
    int*    sCnt   = reinterpret_cast<int*>(sm + SCNT_OFF);
    int*    sLast  = reinterpret_cast<int*>(sm + SLAST_OFF);
    int*    sIdx   = reinterpret_cast<int*>(sm + SIDX_OFF);
    int*    sFq    = reinterpret_cast<int*>(sm + SFQ_OFF);
    int*    sFbi   = reinterpret_cast<int*>(sm + SFBI_OFF);
    float*  sFbest = reinterpret_cast<float*>(sm + SFBEST_OFF);
    float*  sSz    = reinterpret_cast<float*>(sm + SSZ_OFF);
    float*  sSe    = reinterpret_cast<float*>(sm + SSE_OFF);
    float*  sBuf   = reinterpret_cast<float*>(sm + SBUF_OFF);
    float*  sE     = reinterpret_cast<float*>(sm + SE_OFF);

    const int tid  = threadIdx.x;
    const int wid  = tid >> 5;
    const int lane = tid & 31;
    const int qb   = blockIdx.x * QB;

    if (tid == 0) { *sCnt = 0; *sLast = 0; }

    // stage z tile + se
    {
        const float4* src = reinterpret_cast<const float4*>(z + (size_t)qb * DIM);
        #pragma unroll
        for (int i = tid; i < QB * (DIM / 4); i += THREADS) {
            int row = i >> 4, c4 = i & 15;
            float4 v = __ldg(src + row * (DIM / 4) + c4);
            *reinterpret_cast<float4*>(&sBuf[row * PAD + 4 * c4]) = v;
        }
        #pragma unroll
        for (int i = tid; i < K_EMB; i += THREADS) sSe[i] = g_se2[i];
    }
    __syncthreads();

    // row norms + flags
    if (tid < QB) {
        const float* r = &sBuf[tid * PAD];
        float s = 0.0f;
        #pragma unroll
        for (int j = 0; j < DIM; ++j)
            s = __fadd_rn(s, __fmul_rn(r[j], r[j]));
        sSz[tid] = s;

        sFbest[tid] = 3.4e38f;
        sFbi[tid] = 0;
        unsigned v = g_idx[qb + tid];
        sIdx[tid] = (int)(v & 0x3FFu);
        if (v & FLAG_BIT) { int p = atomicAdd(sCnt, 1); sFq[p] = tid; }
    }
    __syncthreads();

    // rescue via smem-staged codebook chunks
    const int cnt = *sCnt;
    if (cnt > 0) {
        for (int ch = 0; ch < K_EMB / QB; ++ch) {
            __syncthreads();
            // stage 128 codes (coalesced LDG, padded STS)
            const float4* src = reinterpret_cast<const float4*>(emb + (size_t)ch * QB * DIM);
            #pragma unroll
            for (int i = tid; i < QB * (DIM / 4); i += THREADS) {
                int row = i >> 4, c4 = i & 15;
                float4 v = __ldg(src + i);
                *reinterpret_cast<float4*>(&sE[row * PAD + 4 * c4]) = v;
            }
            __syncthreads();

            for (int f = wid; f < cnt; f += THREADS / 32) {
                const int q = sFq[f];
                const float szq = sSz[q];
                const float4* zq4 = reinterpret_cast<const float4*>(&sBuf[q * PAD]);
                float best = 3.4e38f; int bi = 0;
                #pragma unroll
                for (int k = 0; k < 4; ++k) {
                    const int cl = k * 32 + lane;
                    const float4* e4 = reinterpret_cast<const float4*>(&sE[cl * PAD]);
                    float a0 = 0.f, a1 = 0.f, a2 = 0.f, a3 = 0.f;
                    #pragma unroll
                    for (int j = 0; j < DIM / 4; ++j) {
                        float4 e = e4[j];
                        float4 zv = zq4[j];        // broadcast LDS.128
                        a0 = fmaf(zv.x, e.x, a0);
                        a1 = fmaf(zv.y, e.y, a1);
                        a2 = fmaf(zv.z, e.z, a2);
                        a3 = fmaf(zv.w, e.w, a3);
                    }
                    float dot = __fadd_rn(__fadd_rn(a0, a1), __fadd_rn(a2, a3));
                    const int c = ch * QB + cl;
                    float d2 = __fadd_rn(__fsub_rn(szq, __fmul_rn(2.0f, dot)), sSe[c]);
                    if (d2 < best) { best = d2; bi = c; }   // ascending c
                }
                #pragma unroll
                for (int off = 16; off > 0; off >>= 1) {
                    float ov = __shfl_down_sync(0xFFFFFFFFu, best, off);
                    int   oi = __shfl_down_sync(0xFFFFFFFFu, bi, off);
                    if (ov < best || (ov == best && oi < bi)) { best = ov; bi = oi; }
                }
                if (lane == 0) {    // merge chunk result (chunks ascending)
                    if (best < sFbest[f] || (best == sFbest[f] && bi < sFbi[f])) {
                        sFbest[f] = best; sFbi[f] = bi;
                    }
                }
            }
        }
        __syncthreads();
        if (tid < cnt) sIdx[sFq[tid]] = sFbi[tid];
        __syncthreads();
    }

    // outputs: gather, STE, idx, loss partial
    double lsum = 0.0;
    if (tid < QB) {
        const int n = qb + tid;
        const int bidx = sIdx[tid];
        const int w = n & 31;
        const int h = (n >> 5) & 31;
        const int b = n >> 10;
        const size_t obase = (size_t)b * 65536 + (size_t)h * 32 + w;

        const float* zr = &sBuf[tid * PAD];
        const float* eb = emb + (size_t)bidx * DIM;
        #pragma unroll
        for (int d = 0; d < DIM; ++d) {
            float zq = zr[d];
            float q  = __ldg(eb + d);
            float diff = __fsub_rn(q, zq);
            out[obase + (size_t)d * 1024] = __fadd_rn(zq, diff);  // STE
            lsum += (double)diff * (double)diff;
        }
        out[OUT_IDX_OFF + (size_t)n] = (float)bidx;
    }

    // block loss reduction + last-block finalize
    #pragma unroll
    for (int off = 16; off > 0; off >>= 1)
        lsum += __shfl_down_sync(0xFFFFFFFFu, lsum, off);
    if (lane == 0) sRed[wid] = lsum;
    __syncthreads();
    if (tid == 0) {
        double v = 0.0;
        #pragma unroll
        for (int i = 0; i < THREADS / 32; ++i) v += sRed[i];
        g_partial[blockIdx.x] = v;
        __threadfence();
        unsigned old = atomicAdd(&g_done, 1u);
        if ((old & (NBLOCKS - 1)) == (NBLOCKS - 1)) *sLast = 1;
    }
    __syncthreads();

    if (*sLast && wid == 0) {
        __threadfence();
        double v = 0.0;
        #pragma unroll
        for (int i = 0; i < NBLOCKS / 32; ++i)
            v += g_partial[lane + i * 32];
        #pragma unroll
        for (int off = 16; off > 0; off >>= 1)
            v += __shfl_down_sync(0xFFFFFFFFu, v, off);
        if (lane == 0) {
            double mean = v / (double)OUT_QV_ELEMS;
            out[OUT_LOSS_OFF] = (float)(mean * 0.25 + mean * 1.0);
        }
    }
}

extern "C" void kernel_launch(void* const* d_in, const int* in_sizes, int n_in,
                              void* d_out, int out_size) {
    const float* z   = (const float*)d_in[0];
    const float* emb = (const float*)d_in[1];
    float* out = (float*)d_out;

    cudaFuncSetAttribute(vq_finish, cudaFuncAttributeMaxDynamicSharedMemorySize, SMEM_FIN);

    vq_prep<<<(NGROUP * 2 * 32 + 255) / 256, 256>>>(emb);
    vq_screen<<<NBLOCKS, THREADS>>>(z);
    vq_finish<<<NBLOCKS, THREADS, SMEM_FIN>>>(z, emb, out);
}